// round 1
// baseline (speedup 1.0000x reference)
#include <cuda_runtime.h>
#include <math.h>

// Problem constants (fixed by the dataset)
#define PN 2        // batch
#define PT 4096     // tokens
#define PD 300      // d_model
#define PH 6        // heads
#define PDH 50      // head dim
#define PTOPK 20

#define CS 68       // padded row stride (floats) for c-major smem tiles (16B aligned, conflict-free)

// Scratch (no cudaMalloc allowed)
__device__ float g_Q[PN * PT * PD];          // projected Q  [N*T, 300]
__device__ float g_K[PN * PT * PD];          // projected K  [N*T, 300]
__device__ float g_maxatt[PH * PN * PT];     // per (head*N+n, key) unscaled max over queries

// ---------------------------------------------------------------------------
// Kernel 1: projection GEMM  C[m,o] = sum_c X[m,c] * W[o,c]   (X:[8192,300], W:[300,300])
// grid: (8192/64, ceil(300/64)=5, 2)   z=0 -> Q, z=1 -> K
// block: 256 threads, 64x64 tile, 4x4 per thread, k-chunks of 50 (6 chunks)
// ---------------------------------------------------------------------------
__global__ __launch_bounds__(256) void proj_kernel(const float* __restrict__ Xq,
                                                   const float* __restrict__ Xk,
                                                   const float* __restrict__ Wq,
                                                   const float* __restrict__ Wk) {
    const float* X = (blockIdx.z == 0) ? Xq : Xk;
    const float* W = (blockIdx.z == 0) ? Wq : Wk;
    float* C       = (blockIdx.z == 0) ? g_Q : g_K;

    const int m0 = blockIdx.x * 64;
    const int o0 = blockIdx.y * 64;

    __shared__ float Xs[PDH][CS];   // c-major: Xs[c][m]
    __shared__ float Ws[PDH][CS];   // c-major: Ws[c][o]

    const int tid   = threadIdx.x;
    const int lane8 = tid & 7;      // c lane
    const int rowg  = tid >> 3;     // 0..31 row group
    const int tx    = tid & 15;     // -> o
    const int ty    = tid >> 4;     // -> m

    float acc[4][4];
#pragma unroll
    for (int i = 0; i < 4; ++i)
#pragma unroll
        for (int j = 0; j < 4; ++j) acc[i][j] = 0.f;

    for (int kc = 0; kc < PD / PDH; ++kc) {   // 6 chunks of 50
        __syncthreads();
#pragma unroll
        for (int pass = 0; pass < 2; ++pass) {
            const int r = rowg + 32 * pass;            // 0..63
            const float* xsrc = X + (size_t)(m0 + r) * PD + kc * PDH;
#pragma unroll
            for (int i = 0; i < 7; ++i) {
                const int c = lane8 + i * 8;
                if (c < PDH) Xs[c][r] = xsrc[c];
            }
            const int o = o0 + r;
            const float* wsrc = W + (size_t)o * PD + kc * PDH;
#pragma unroll
            for (int i = 0; i < 7; ++i) {
                const int c = lane8 + i * 8;
                if (c < PDH) Ws[c][r] = (o < PD) ? wsrc[c] : 0.f;
            }
        }
        __syncthreads();

#pragma unroll 10
        for (int c = 0; c < PDH; ++c) {
            const float4 xv = *reinterpret_cast<const float4*>(&Xs[c][ty * 4]);
            const float4 wv = *reinterpret_cast<const float4*>(&Ws[c][tx * 4]);
            acc[0][0] += xv.x * wv.x; acc[0][1] += xv.x * wv.y; acc[0][2] += xv.x * wv.z; acc[0][3] += xv.x * wv.w;
            acc[1][0] += xv.y * wv.x; acc[1][1] += xv.y * wv.y; acc[1][2] += xv.y * wv.z; acc[1][3] += xv.y * wv.w;
            acc[2][0] += xv.z * wv.x; acc[2][1] += xv.z * wv.y; acc[2][2] += xv.z * wv.z; acc[2][3] += xv.z * wv.w;
            acc[3][0] += xv.w * wv.x; acc[3][1] += xv.w * wv.y; acc[3][2] += xv.w * wv.z; acc[3][3] += xv.w * wv.w;
        }
    }

#pragma unroll
    for (int i = 0; i < 4; ++i) {
        const int m = m0 + ty * 4 + i;
#pragma unroll
        for (int j = 0; j < 4; ++j) {
            const int o = o0 + tx * 4 + j;
            if (o < PD) C[(size_t)m * PD + o] = acc[i][j];
        }
    }
}

// ---------------------------------------------------------------------------
// Kernel 2: maxatt[b][k] = max_q  dot(Q_b[q], K_b[k])   (unscaled)
// b = head*N + n.   Q_b[q][j] = g_Q[(n*T+q)*300 + head*50 + j]
// grid: (T/64 key tiles, 12)   block: 256 threads
// K tile (64 keys x 50) resident in smem for whole block; stream Q in 64-row tiles.
// 4x4 microtile, running max over q per key.
// ---------------------------------------------------------------------------
__global__ __launch_bounds__(256) void scores_max_kernel() {
    const int kt   = blockIdx.x;          // key tile
    const int b    = blockIdx.y;          // 0..11
    const int head = b / PN;
    const int n    = b % PN;

    const float* Kbase = g_K + (size_t)n * PT * PD + head * PDH;
    const float* Qbase = g_Q + (size_t)n * PT * PD + head * PDH;

    __shared__ float Ks[PDH][CS];   // c-major [c][key]
    __shared__ float Qs[PDH][CS];   // c-major [c][q]

    const int tid   = threadIdx.x;
    const int lane8 = tid & 7;
    const int rowg  = tid >> 3;
    const int tx    = tid & 15;     // -> q
    const int ty    = tid >> 4;     // -> key

    // load K tile once
#pragma unroll
    for (int pass = 0; pass < 2; ++pass) {
        const int r = rowg + 32 * pass;
        const float* src = Kbase + (size_t)(kt * 64 + r) * PD;
#pragma unroll
        for (int i = 0; i < 7; ++i) {
            const int c = lane8 + i * 8;
            if (c < PDH) Ks[c][r] = src[c];
        }
    }

    float kmax[4];
#pragma unroll
    for (int i = 0; i < 4; ++i) kmax[i] = -3.0e38f;

    for (int qt = 0; qt < PT / 64; ++qt) {
        __syncthreads();   // protects Ks on first iter, Qs reuse afterwards
#pragma unroll
        for (int pass = 0; pass < 2; ++pass) {
            const int r = rowg + 32 * pass;
            const float* src = Qbase + (size_t)(qt * 64 + r) * PD;
#pragma unroll
            for (int i = 0; i < 7; ++i) {
                const int c = lane8 + i * 8;
                if (c < PDH) Qs[c][r] = src[c];
            }
        }
        __syncthreads();

        float acc[4][4];
#pragma unroll
        for (int i = 0; i < 4; ++i)
#pragma unroll
            for (int j = 0; j < 4; ++j) acc[i][j] = 0.f;

#pragma unroll 10
        for (int c = 0; c < PDH; ++c) {
            const float4 kv = *reinterpret_cast<const float4*>(&Ks[c][ty * 4]);
            const float4 qv = *reinterpret_cast<const float4*>(&Qs[c][tx * 4]);
            acc[0][0] += kv.x * qv.x; acc[0][1] += kv.x * qv.y; acc[0][2] += kv.x * qv.z; acc[0][3] += kv.x * qv.w;
            acc[1][0] += kv.y * qv.x; acc[1][1] += kv.y * qv.y; acc[1][2] += kv.y * qv.z; acc[1][3] += kv.y * qv.w;
            acc[2][0] += kv.z * qv.x; acc[2][1] += kv.z * qv.y; acc[2][2] += kv.z * qv.z; acc[2][3] += kv.z * qv.w;
            acc[3][0] += kv.w * qv.x; acc[3][1] += kv.w * qv.y; acc[3][2] += kv.w * qv.z; acc[3][3] += kv.w * qv.w;
        }

#pragma unroll
        for (int i = 0; i < 4; ++i) {
            float m = fmaxf(fmaxf(acc[i][0], acc[i][1]), fmaxf(acc[i][2], acc[i][3]));
            kmax[i] = fmaxf(kmax[i], m);
        }
    }

    // reduce across the 16 q-threads sharing each key (lanes differ only in tx bits 0..3)
#pragma unroll
    for (int off = 8; off; off >>= 1) {
#pragma unroll
        for (int i = 0; i < 4; ++i)
            kmax[i] = fmaxf(kmax[i], __shfl_xor_sync(0xffffffffu, kmax[i], off));
    }
    if (tx == 0) {
#pragma unroll
        for (int i = 0; i < 4; ++i)
            g_maxatt[(size_t)b * PT + kt * 64 + ty * 4 + i] = kmax[i];
    }
}

// ---------------------------------------------------------------------------
// Kernel 3: per b: top-20 of maxatt (ties -> lowest index), softmax(scaled),
// weighted sum of gathered K rows. Output: out[n, head*50 + j].
// grid: 12 blocks x 128 threads
// ---------------------------------------------------------------------------
__global__ __launch_bounds__(128) void select_kernel(float* __restrict__ out) {
    const int b    = blockIdx.x;
    const int head = b / PN;
    const int n    = b % PN;
    const int tid  = threadIdx.x;

    __shared__ float vals[PT];        // 16KB working copy
    __shared__ float bestv[128];
    __shared__ int   besti[128];
    __shared__ float topv[PTOPK];
    __shared__ int   topi[PTOPK];
    __shared__ float probs[PTOPK];

    for (int i = tid; i < PT; i += 128) vals[i] = g_maxatt[(size_t)b * PT + i];
    __syncthreads();

    for (int sel = 0; sel < PTOPK; ++sel) {
        float bv = -3.0e38f;
        int   bi = 0x7fffffff;
        for (int i = tid; i < PT; i += 128) {
            const float v = vals[i];
            if (v > bv || (v == bv && i < bi)) { bv = v; bi = i; }
        }
        bestv[tid] = bv; besti[tid] = bi;
        __syncthreads();
        for (int s = 64; s; s >>= 1) {
            if (tid < s) {
                const float v2 = bestv[tid + s];
                const int   i2 = besti[tid + s];
                if (v2 > bestv[tid] || (v2 == bestv[tid] && i2 < besti[tid])) {
                    bestv[tid] = v2; besti[tid] = i2;
                }
            }
            __syncthreads();
        }
        if (tid == 0) {
            topv[sel] = bestv[0];
            topi[sel] = besti[0];
            vals[besti[0]] = -3.0e38f;   // mask out
        }
        __syncthreads();
    }

    if (tid == 0) {
        const float inv = rsqrtf((float)PDH);     // 1/sqrt(50)
        float s = 0.f;
        float e[PTOPK];
#pragma unroll
        for (int i = 0; i < PTOPK; ++i) {
            e[i] = expf((topv[i] - topv[0]) * inv);   // topv[0] is the max
            s += e[i];
        }
        const float invs = 1.0f / s;
#pragma unroll
        for (int i = 0; i < PTOPK; ++i) probs[i] = e[i] * invs;
    }
    __syncthreads();

    for (int j = tid; j < PDH; j += 128) {
        float acc = 0.f;
#pragma unroll
        for (int i = 0; i < PTOPK; ++i)
            acc += probs[i] * g_K[((size_t)n * PT + topi[i]) * PD + head * PDH + j];
        out[(size_t)n * PD + head * PDH + j] = acc;
    }
}

// ---------------------------------------------------------------------------
extern "C" void kernel_launch(void* const* d_in, const int* in_sizes, int n_in,
                              void* d_out, int out_size) {
    const float* querys = (const float*)d_in[0];
    const float* keys   = (const float*)d_in[1];
    // d_in[2] = values  : UNUSED by the reference's output path
    const float* Wq     = (const float*)d_in[3];
    const float* Wk     = (const float*)d_in[4];
    // d_in[5] = Wv      : unused
    // d_in[6] = num_heads (hardcoded 6)

    dim3 gproj(PN * PT / 64, (PD + 63) / 64, 2);
    proj_kernel<<<gproj, 256>>>(querys, keys, Wq, Wk);

    dim3 gsc(PT / 64, PH * PN);
    scores_max_kernel<<<gsc, 256>>>();

    select_kernel<<<PH * PN, 128>>>((float*)d_out);
}